// round 13
// baseline (speedup 1.0000x reference)
#include <cuda_runtime.h>
#include <cuda_bf16.h>
#include <cstdint>
#include <cstddef>

typedef unsigned long long ull;
typedef unsigned short u16;

// Problem constants
#define BB   32
#define NE   512
#define ND   512
#define VOC  2000
#define HH   256
#define FF   256
#define PP   4
#define EE   128

// ---------------- scratch (device globals; no allocations allowed) ----------------
__device__ __align__(16) u16 g_epad_bf[(size_t)BB * 516 * FF];
__device__ __align__(16) u16 g_t_bf[(size_t)BB * NE * FF];
__device__ float g_logits[(size_t)BB * NE * VOC];
__device__ float g_rmax[BB * NE];
__device__ float g_rsum[BB * NE];
__device__ float g_S[(size_t)BB * ND * NE];               // (b, j, i)
__device__ __align__(16) u16 g_xemb_bf[(size_t)BB * NE * EE];
__device__ __align__(16) u16 g_yemb_bf[(size_t)BB * ND * EE];
__device__ float g_xz[(size_t)BB * NE * 4 * HH];
__device__ float g_yz[(size_t)BB * ND * 4 * HH];
__device__ __align__(16) uint4 g_WencP4[32 * 1024];       // Whh bf16x2, [kk][row]
__device__ __align__(16) uint4 g_WdecP4[32 * 1024];
__device__ __align__(16) u16 g_gconv_bf[5 * FF * FF];     // 1280 x 256
__device__ __align__(16) u16 g_gdec_bf[FF * VOC];         // 256 x 2000
__device__ __align__(16) u16 g_wihE_bf[4 * HH * EE];      // 1024 x 128
__device__ __align__(16) u16 g_wihD_bf[4 * HH * EE];
__device__ __align__(16) u16 g_T_bf[HH * 2 * HH];         // 256 x 512
__device__ __align__(16) u16 g_hcat_bf[(size_t)BB * NE * 2 * HH];
__device__ float g_cT[BB * HH];
__device__ __align__(16) u16 g_hdec_bf[(size_t)BB * ND * HH];
__device__ __align__(16) u16 g_Th_bf[(size_t)BB * NE * HH];
__device__ float g_E[(size_t)BB * ND * NE];               // (b, j, i)
__device__ float g_p[BB * ND];

// ---------------- common helpers ----------------
__device__ __forceinline__ float sigf(float x) { return 1.f / (1.f + expf(-x)); }
__device__ __forceinline__ unsigned smem_u32(const void* p)
{
    unsigned a;
    asm("{ .reg .u64 t; cvta.to.shared.u64 t, %1; cvt.u32.u64 %0, t; }" : "=r"(a) : "l"(p));
    return a;
}
__device__ __forceinline__ void mma16816(float* c,
                                         unsigned a0, unsigned a1, unsigned a2, unsigned a3,
                                         unsigned b0, unsigned b1)
{
    asm("mma.sync.aligned.m16n8k16.row.col.f32.bf16.bf16.f32 "
        "{%0,%1,%2,%3}, {%4,%5,%6,%7}, {%8,%9}, {%0,%1,%2,%3};"
        : "+f"(c[0]), "+f"(c[1]), "+f"(c[2]), "+f"(c[3])
        : "r"(a0), "r"(a1), "r"(a2), "r"(a3), "r"(b0), "r"(b1));
}
__device__ __forceinline__ void ldsm4(unsigned& r0, unsigned& r1, unsigned& r2, unsigned& r3,
                                      unsigned addr)
{
    asm volatile("ldmatrix.sync.aligned.m8n8.x4.shared.b16 {%0,%1,%2,%3}, [%4];"
                 : "=r"(r0), "=r"(r1), "=r"(r2), "=r"(r3) : "r"(addr));
}
__device__ __forceinline__ void ldsm4t(unsigned& r0, unsigned& r1, unsigned& r2, unsigned& r3,
                                       unsigned addr)
{
    asm volatile("ldmatrix.sync.aligned.m8n8.x4.trans.shared.b16 {%0,%1,%2,%3}, [%4];"
                 : "=r"(r0), "=r"(r1), "=r"(r2), "=r"(r3) : "r"(addr));
}

// ---------------- bf16 tensor-core GEMM (unchanged R8/R9 winner) ----------------
template <int EPI, bool TB>
__global__ void __launch_bounds__(256) hgemm(
    const u16* __restrict__ A, size_t sAz, int lda,
    const u16* __restrict__ B, size_t sBz, int ldb,
    void* __restrict__ C, size_t sCz, int ldc,
    int M, int N, int K, const float* __restrict__ bias)
{
    __shared__ __align__(16) char smem[20480];
    char* smA = smem;
    char* smB = smem + 10240;

    const u16* Ab = A + blockIdx.z * sAz;
    const u16* Bb = B + blockIdx.z * sBz;

    const int bm0 = blockIdx.y * 128;
    const int bn0 = blockIdx.x * 128;
    const int tid = threadIdx.x;
    const int w = tid >> 5, lane = tid & 31;
    const int wm = w >> 1, wn = w & 1;
    const int sel = lane >> 3, lr = lane & 7;

    float acc[2][8][4];
#pragma unroll
    for (int mi = 0; mi < 2; mi++)
#pragma unroll
        for (int nf = 0; nf < 8; nf++)
#pragma unroll
            for (int i = 0; i < 4; i++) acc[mi][nf][i] = 0.f;

    unsigned aA = smem_u32(smA);
    unsigned aB = aA + 10240;

    const int arow = wm * 32 + lr + (sel & 1) * 8;
    const int aksl = (sel >> 1) * 8;
    const int ntrow = wn * 64 + lr + (sel >> 1) * 8;
    const int ntksl = (sel & 1) * 8;
    const int nnksl = lr + (sel & 1) * 8;
    const int nnnof = wn * 64 + (sel >> 1) * 8;

    for (int k0 = 0; k0 < K; k0 += 32) {
#pragma unroll
        for (int j = 0; j < 2; j++) {
            int idx = tid + 256 * j;
            int row = idx >> 2, grp = idx & 3;
            uint4 v = *(const uint4*)(Ab + (size_t)(bm0 + row) * lda + k0 + grp * 8);
            *(uint4*)(smA + row * 80 + grp * 16) = v;
        }
        if (TB) {
#pragma unroll
            for (int j = 0; j < 2; j++) {
                int idx = tid + 256 * j;
                int row = idx >> 2, grp = idx & 3;
                uint4 v = *(const uint4*)(Bb + (size_t)(bn0 + row) * ldb + k0 + grp * 8);
                *(uint4*)(smB + row * 80 + grp * 16) = v;
            }
        } else {
#pragma unroll
            for (int j = 0; j < 2; j++) {
                int idx = tid + 256 * j;
                int k = idx >> 4, ngrp = idx & 15;
                int n0c = bn0 + ngrp * 8;
                uint4 v = make_uint4(0u, 0u, 0u, 0u);
                if (n0c + 8 <= N) v = *(const uint4*)(Bb + (size_t)(k0 + k) * ldb + n0c);
                *(uint4*)(smB + k * 272 + ngrp * 16) = v;
            }
        }
        __syncthreads();

#pragma unroll
        for (int q = 0; q < 32; q += 16) {
            unsigned a[2][4];
#pragma unroll
            for (int mi = 0; mi < 2; mi++)
                ldsm4(a[mi][0], a[mi][1], a[mi][2], a[mi][3],
                      aA + (unsigned)((arow + mi * 16) * 80 + (q + aksl) * 2));
#pragma unroll
            for (int nf2 = 0; nf2 < 4; nf2++) {
                unsigned b0, b1, b2, b3;
                if (TB) {
                    ldsm4(b0, b1, b2, b3,
                          aB + (unsigned)((ntrow + nf2 * 16) * 80 + (q + ntksl) * 2));
                } else {
                    ldsm4t(b0, b1, b2, b3,
                           aB + (unsigned)((q + nnksl) * 272 + (nnnof + nf2 * 16) * 2));
                }
#pragma unroll
                for (int mi = 0; mi < 2; mi++) {
                    mma16816(acc[mi][2 * nf2], a[mi][0], a[mi][1], a[mi][2], a[mi][3], b0, b1);
                    mma16816(acc[mi][2 * nf2 + 1], a[mi][0], a[mi][1], a[mi][2], a[mi][3], b2, b3);
                }
            }
        }
        __syncthreads();
    }

    const int er = bm0 + wm * 32 + (lane >> 2);
    const int ec = bn0 + wn * 64 + (lane & 3) * 2;
#pragma unroll
    for (int mi = 0; mi < 2; mi++) {
#pragma unroll
        for (int nf = 0; nf < 8; nf++) {
            int col = ec + nf * 8;
            if (col >= N) continue;
#pragma unroll
            for (int half = 0; half < 2; half++) {
                int row = er + mi * 16 + half * 8;
                float v0 = acc[mi][nf][2 * half];
                float v1 = acc[mi][nf][2 * half + 1];
                if (EPI == 0) {
                    float2 o = make_float2(v0, v1);
                    *(float2*)((float*)C + (size_t)blockIdx.z * sCz + (size_t)row * ldc + col) = o;
                } else if (EPI == 2) {
                    float2 o = make_float2(v0 + bias[col], v1 + bias[col + 1]);
                    *(float2*)((float*)C + (size_t)blockIdx.z * sCz + (size_t)row * ldc + col) = o;
                } else {
                    float w0 = (EPI == 1) ? tanhf(v0) : v0;
                    float w1 = (EPI == 1) ? tanhf(v1) : v1;
                    __nv_bfloat162 o = __floats2bfloat162_rn(w0, w1);
                    *(__nv_bfloat162*)((u16*)C + (size_t)blockIdx.z * sCz + (size_t)row * ldc + col) = o;
                }
            }
        }
    }
}

// ---------------- prep kernels ----------------
__device__ __forceinline__ u16 f2b(float x) { return __bfloat16_as_ushort(__float2bfloat16(x)); }

__global__ void k_epad(const int* __restrict__ xs, const float* __restrict__ gembed)
{
    int idx = blockIdx.x * 256 + threadIdx.x;
    if (idx >= BB * 516 * FF) return;
    int f = idx & 255;
    int rest = idx >> 8;
    int ip = rest % 516;
    int b = rest / 516;
    float v = 0.f;
    int i = ip - 2;
    if (i >= 0 && i < NE) {
        int id = xs[b * NE + i];
        v = tanhf(gembed[(size_t)id * FF + f]);
    }
    g_epad_bf[idx] = f2b(v);
}

__global__ void k_emb(const int* __restrict__ xs, const int* __restrict__ ys,
                      const float* __restrict__ enc_e, const float* __restrict__ dec_e)
{
    int idx = blockIdx.x * 256 + threadIdx.x;
    if (idx >= BB * NE * EE) return;
    int f = idx & 127;
    int r = idx >> 7;
    int xi = xs[r]; if (xi < PP) xi = 0;
    g_xemb_bf[idx] = f2b(enc_e[(size_t)xi * EE + f]);
    int yi = ys[r]; if (yi < PP) yi = 0;
    g_yemb_bf[idx] = f2b(dec_e[(size_t)yi * EE + f]);
}

__global__ void k_cvt(const float* __restrict__ gconv, const float* __restrict__ gdec,
                      const float* __restrict__ wE, const float* __restrict__ wD,
                      const float* __restrict__ T)
{
    int i = blockIdx.x * 256 + threadIdx.x;
    if (i < 5 * FF * FF) g_gconv_bf[i] = f2b(gconv[i]);
    if (i < FF * VOC)    g_gdec_bf[i]  = f2b(gdec[i]);
    if (i < 4 * HH * EE) { g_wihE_bf[i] = f2b(wE[i]); g_wihD_bf[i] = f2b(wD[i]); }
    if (i < HH * 2 * HH) g_T_bf[i] = f2b(T[i]);
}

__device__ __forceinline__ unsigned pack_bf2(float a, float b)
{
    return (unsigned)f2b(a) | ((unsigned)f2b(b) << 16);
}

__global__ void k_pack(const float* __restrict__ We, const float* __restrict__ Wd)
{
    int idx = blockIdx.x * 256 + threadIdx.x;
    if (idx >= 32 * 1024) return;
    int kk = idx >> 10, n = idx & 1023;
    const float* re = We + (size_t)n * 256 + 8 * kk;
    const float* rd = Wd + (size_t)n * 256 + 8 * kk;
    uint4 ve, vd;
    ve.x = pack_bf2(re[0], re[1]); ve.y = pack_bf2(re[2], re[3]);
    ve.z = pack_bf2(re[4], re[5]); ve.w = pack_bf2(re[6], re[7]);
    vd.x = pack_bf2(rd[0], rd[1]); vd.y = pack_bf2(rd[2], rd[3]);
    vd.z = pack_bf2(rd[4], rd[5]); vd.w = pack_bf2(rd[6], rd[7]);
    g_WencP4[idx] = ve;
    g_WdecP4[idx] = vd;
}

// ---------------- softmax row stats over vocab ----------------
__global__ void k_rowstats()
{
    int row = blockIdx.x;
    const float* L = g_logits + (size_t)row * VOC;
    int t = threadIdx.x;
    __shared__ float red[256];
    float m = -1e30f;
    for (int v = t; v < VOC; v += 256) m = fmaxf(m, L[v]);
    red[t] = m; __syncthreads();
    for (int s = 128; s > 0; s >>= 1) { if (t < s) red[t] = fmaxf(red[t], red[t + s]); __syncthreads(); }
    m = red[0];
    __syncthreads();
    float s = 0.f;
    for (int v = t; v < VOC; v += 256) s += expf(L[v] - m);
    red[t] = s; __syncthreads();
    for (int sr = 128; sr > 0; sr >>= 1) { if (t < sr) red[t] += red[t + sr]; __syncthreads(); }
    if (t == 0) { g_rmax[row] = m; g_rsum[row] = red[0]; }
}

__global__ void k_scores(const int* __restrict__ ys)
{
    int bj = blockIdx.x;
    int b = bj >> 9;
    int v = ys[bj];
    int i = threadIdx.x;
    size_t row = (size_t)b * NE + i;
    float l = g_logits[row * VOC + v];
    g_S[(size_t)bj * NE + i] = expf(l - g_rmax[row]) / g_rsum[row];
}

// ---------------- LSTM: mma.sync, reg-stationary W, mbarrier step sync ----------------
#define CLUSTER_BAR() do { \
    asm volatile("barrier.cluster.arrive.aligned;" ::: "memory"); \
    asm volatile("barrier.cluster.wait.aligned;" ::: "memory"); } while (0)

__device__ __forceinline__ void st_peer32(unsigned off, int rank, unsigned v)
{
    unsigned ra;
    asm volatile("mapa.shared::cluster.u32 %0, %1, %2;" : "=r"(ra) : "r"(off), "r"(rank));
    asm volatile("st.shared::cluster.b32 [%0], %1;" :: "r"(ra), "r"(v) : "memory");
}

#define MBAR_INIT(addr, cnt) \
    asm volatile("mbarrier.init.shared.b64 [%0], %1;" :: "r"(addr), "r"(cnt) : "memory")

__device__ __forceinline__ void mbar_arrive_peer(unsigned local_addr, unsigned rank)
{
    unsigned ra;
    asm volatile("mapa.shared::cluster.u32 %0, %1, %2;" : "=r"(ra) : "r"(local_addr), "r"(rank));
    asm volatile("mbarrier.arrive.release.cluster.shared::cluster.b64 _, [%0];"
                 :: "r"(ra) : "memory");
}

__device__ __forceinline__ void mbar_wait_parity(unsigned addr, unsigned parity)
{
    asm volatile(
        "{\n\t"
        ".reg .pred P;\n"
        "WAIT_%=:\n\t"
        "mbarrier.try_wait.parity.acquire.cluster.shared::cta.b64 P, [%0], %1, 0x989680;\n\t"
        "@!P bra WAIT_%=;\n\t"
        "}"
        :: "r"(addr), "r"(parity) : "memory");
}

#define HCOLW 136   // words per h column; paired layout, conflict-free LDS.64
#define SZS   260   // s_z column stride (floats)

// paired word index for hidden unit k: word holds (h[k&~1], h[k|1])
__device__ __forceinline__ int pw_idx(int k)
{
    int w = (k >> 1) & 7;
    return (k >> 4) * 8 + (w & 3) * 2 + (w >> 2);
}

// Single-direction encoder pass. DIR=0 forward (also writes g_cT at final step),
// DIR=1 backward. 8 clusters x 4 CTAs (grid 32). Cluster = 4 batches (cols 0..3).
template <int DIR>
__global__ void __launch_bounds__(512, 1) __cluster_dims__(4, 1, 1) lstm_dir_mma()
{
    __shared__ __align__(16) unsigned s_h[2 * 8 * HCOLW];
    __shared__ float s_x[1024];
    __shared__ float s_z[8 * SZS];
    __shared__ float s_c[256];
    __shared__ __align__(8) ull s_mb[2];

    unsigned rank; asm("mov.u32 %0, %%cluster_ctarank;" : "=r"(rank));
    int cl = blockIdx.x >> 2;
    int t = threadIdx.x;
    int w = t >> 5, lane = t & 31, g = lane >> 2, t4 = lane & 3;
    int mb = w & 7, kh = w >> 3;
    int r1 = 32 * mb + g, r2 = r1 + 8, r3 = r1 + 16, r4 = r1 + 24;
    int R1 = ((r1 >> 6) << 8) + (int)(rank << 6) + (r1 & 63);
    int R2 = ((r2 >> 6) << 8) + (int)(rank << 6) + (r2 & 63);
    int R3 = ((r3 >> 6) << 8) + (int)(rank << 6) + (r3 & 63);
    int R4 = ((r4 >> 6) << 8) + (int)(rank << 6) + (r4 & 63);

    unsigned areg0[32], areg1[32];
    const unsigned* WP = (const unsigned*)g_WencP4;
#pragma unroll
    for (int kt = 0; kt < 8; kt++) {
        int j = 8 * kh + kt;
        areg0[4 * kt + 0] = WP[(((2 * j) * 1024 + R1) << 2) + t4];
        areg0[4 * kt + 1] = WP[(((2 * j) * 1024 + R2) << 2) + t4];
        areg0[4 * kt + 2] = WP[(((2 * j + 1) * 1024 + R1) << 2) + t4];
        areg0[4 * kt + 3] = WP[(((2 * j + 1) * 1024 + R2) << 2) + t4];
        areg1[4 * kt + 0] = WP[(((2 * j) * 1024 + R3) << 2) + t4];
        areg1[4 * kt + 1] = WP[(((2 * j) * 1024 + R4) << 2) + t4];
        areg1[4 * kt + 2] = WP[(((2 * j + 1) * 1024 + R3) << 2) + t4];
        areg1[4 * kt + 3] = WP[(((2 * j + 1) * 1024 + R4) << 2) + t4];
    }

    // x prefetch
    int c0i = t >> 8, row0 = t & 255;
    int c1i = (t + 512) >> 8;
    int b0i = 4 * cl + c0i, b1i = 4 * cl + c1i;
    int Gr0 = ((row0 >> 6) << 8) + (int)(rank << 6) + (row0 & 63);
    const float* xp0 = g_xz + ((size_t)b0i * NE + (DIR ? 511 : 0)) * 1024 + Gr0;
    const float* xp1 = g_xz + ((size_t)b1i * NE + (DIR ? 511 : 0)) * 1024 + Gr0;
    const int xstride = DIR ? -1024 : 1024;
    float xv0 = *xp0, xv1 = *xp1;

    for (int i = t; i < 2 * 8 * HCOLW; i += 512) s_h[i] = 0;
    if (t < 256) s_c[t] = 0.f;
    unsigned mb_sh = smem_u32(s_mb);
    if (t == 0) { MBAR_INIT(mb_sh, 32); MBAR_INIT(mb_sh + 8, 32); }
    __syncthreads();
    CLUSTER_BAR();

    unsigned h_sh = smem_u32(s_h);

    int mycol = t >> 6, myu = t & 63;
    int myb = 4 * cl + mycol;
    int myk = (int)(rank << 6) + myu;
    unsigned stcol = (unsigned)((mycol * HCOLW + pw_idx(myk)) << 2);

    for (int step = 0; step < 512; step++) {
        int ph = step & 1;
        int tt = DIR ? (511 - step) : step;

        s_x[t] = xv0;
        s_x[t + 512] = xv1;
        if (step < 511) { xp0 += xstride; xv0 = *xp0; xp1 += xstride; xv1 = *xp1; }

        float e[4] = {0.f, 0.f, 0.f, 0.f};
        float o[4] = {0.f, 0.f, 0.f, 0.f};
        const ull* hw64 = (const ull*)(s_h + ph * 8 * HCOLW + g * HCOLW);
#pragma unroll
        for (int kt = 0; kt < 8; kt++) {
            ull v = hw64[4 * (8 * kh + kt) + t4];
            unsigned blo = (unsigned)v, bhi = (unsigned)(v >> 32);
            mma16816(e, areg0[4 * kt], areg0[4 * kt + 1], areg0[4 * kt + 2], areg0[4 * kt + 3], blo, bhi);
            mma16816(o, areg1[4 * kt], areg1[4 * kt + 1], areg1[4 * kt + 2], areg1[4 * kt + 3], blo, bhi);
        }
        if (t4 < 2) {
            float* zb = s_z + kh * (4 * SZS);
            int cb = 2 * t4;
            zb[cb * SZS + r1]       = e[0];
            zb[(cb + 1) * SZS + r1] = e[1];
            zb[cb * SZS + r2]       = e[2];
            zb[(cb + 1) * SZS + r2] = e[3];
            zb[cb * SZS + r3]       = o[0];
            zb[(cb + 1) * SZS + r3] = o[1];
            zb[cb * SZS + r4]       = o[2];
            zb[(cb + 1) * SZS + r4] = o[3];
        }
        __syncthreads();
        unsigned mbq = mb_sh + (unsigned)((step & 1) << 3);
        if (t < 256) {
            const float* z0 = s_z + mycol * SZS;
            const float* z1 = s_z + 4 * SZS + mycol * SZS;
            const float* x = s_x + mycol * 256;
            float zi = z0[myu]       + z1[myu]       + x[myu];
            float zf = z0[64 + myu]  + z1[64 + myu]  + x[64 + myu];
            float zg = z0[128 + myu] + z1[128 + myu] + x[128 + myu];
            float zo = z0[192 + myu] + z1[192 + myu] + x[192 + myu];
            float cc = sigf(zf) * s_c[t] + sigf(zi) * tanhf(zg);
            float hh = sigf(zo) * tanhf(cc);
            s_c[t] = cc;
            u16 h16 = f2b(hh);
            g_hcat_bf[((size_t)myb * NE + tt) * 512 + DIR * 256 + myk] = h16;
            if (DIR == 0 && step == 511) g_cT[myb * 256 + myk] = cc;
            unsigned pn = __shfl_down_sync(0xffffffffu, (unsigned)h16, 1);
            if (!(myu & 1)) {
                unsigned pk = (unsigned)h16 | (pn << 16);
                unsigned off = h_sh + (unsigned)((ph ^ 1) * 8 * HCOLW * 4) + stcol;
                st_peer32(off, 0, pk);
                st_peer32(off, 1, pk);
                st_peer32(off, 2, pk);
                st_peer32(off, 3, pk);
            }
            __syncwarp();
            if (lane == 0) {
                mbar_arrive_peer(mbq, 0);
                mbar_arrive_peer(mbq, 1);
                mbar_arrive_peer(mbq, 2);
                mbar_arrive_peer(mbq, 3);
            }
        }
        mbar_wait_parity(mbq, (unsigned)((step >> 1) & 1));
    }
    CLUSTER_BAR();
}

// Decoder: 8 clusters x 4 CTAs (grid 32). Cluster = 4 batches (cols 0..3).
__global__ void __launch_bounds__(512, 1) __cluster_dims__(4, 1, 1) lstm_dec_mma()
{
    __shared__ __align__(16) unsigned s_h[2 * 8 * HCOLW];
    __shared__ float s_x[1024];
    __shared__ float s_z[8 * SZS];
    __shared__ float s_c[256];
    __shared__ __align__(8) ull s_mb[2];

    unsigned rank; asm("mov.u32 %0, %%cluster_ctarank;" : "=r"(rank));
    int cl = blockIdx.x >> 2;
    int t = threadIdx.x;
    int w = t >> 5, lane = t & 31, g = lane >> 2, t4 = lane & 3;
    int mb = w & 7, kh = w >> 3;
    int r1 = 32 * mb + g, r2 = r1 + 8, r3 = r1 + 16, r4 = r1 + 24;
    int R1 = ((r1 >> 6) << 8) + (int)(rank << 6) + (r1 & 63);
    int R2 = ((r2 >> 6) << 8) + (int)(rank << 6) + (r2 & 63);
    int R3 = ((r3 >> 6) << 8) + (int)(rank << 6) + (r3 & 63);
    int R4 = ((r4 >> 6) << 8) + (int)(rank << 6) + (r4 & 63);

    unsigned areg0[32], areg1[32];
    const unsigned* WP = (const unsigned*)g_WdecP4;
#pragma unroll
    for (int kt = 0; kt < 8; kt++) {
        int j = 8 * kh + kt;
        areg0[4 * kt + 0] = WP[(((2 * j) * 1024 + R1) << 2) + t4];
        areg0[4 * kt + 1] = WP[(((2 * j) * 1024 + R2) << 2) + t4];
        areg0[4 * kt + 2] = WP[(((2 * j + 1) * 1024 + R1) << 2) + t4];
        areg0[4 * kt + 3] = WP[(((2 * j + 1) * 1024 + R2) << 2) + t4];
        areg1[4 * kt + 0] = WP[(((2 * j) * 1024 + R3) << 2) + t4];
        areg1[4 * kt + 1] = WP[(((2 * j) * 1024 + R4) << 2) + t4];
        areg1[4 * kt + 2] = WP[(((2 * j + 1) * 1024 + R3) << 2) + t4];
        areg1[4 * kt + 3] = WP[(((2 * j + 1) * 1024 + R4) << 2) + t4];
    }

    // x prefetch
    int c0i = t >> 8, row0 = t & 255;
    int c1i = (t + 512) >> 8;
    int b0i = 4 * cl + c0i, b1i = 4 * cl + c1i;
    int Gr0 = ((row0 >> 6) << 8) + (int)(rank << 6) + (row0 & 63);
    const float* xp0 = g_yz + (size_t)b0i * ND * 1024 + Gr0;
    const float* xp1 = g_yz + (size_t)b1i * ND * 1024 + Gr0;
    float xv0 = *xp0, xv1 = *xp1;

    for (int i = t; i < 2 * 8 * HCOLW; i += 512) s_h[i] = 0;
    unsigned mb_sh = smem_u32(s_mb);
    if (t == 0) { MBAR_INIT(mb_sh, 32); MBAR_INIT(mb_sh + 8, 32); }
    __syncthreads();
    // init h0 (paired layout, buf0 cols 0..3), hdec[:,0], c0
    for (int idx = t; idx < 1024; idx += 512) {
        int col = idx >> 8, k = idx & 255;
        int b = 4 * cl + col;
        u16 hb = g_hcat_bf[((size_t)b * NE + 511) * 512 + k];
        ((u16*)s_h)[(col * HCOLW + pw_idx(k)) * 2 + (k & 1)] = hb;
        if (rank == 0) g_hdec_bf[(size_t)b * ND * HH + k] = hb;
    }
    __shared__ float s_c_init_guard[1];
    (void)s_c_init_guard;
    if (t < 256) {
        int col = t >> 6, u = t & 63;
        s_c[t] = g_cT[(4 * cl + col) * 256 + (int)(rank << 6) + u];
    }
    __syncthreads();
    CLUSTER_BAR();

    unsigned h_sh = smem_u32(s_h);

    int mycol = t >> 6, myu = t & 63;
    int myb = 4 * cl + mycol;
    int myk = (int)(rank << 6) + myu;
    unsigned stcol = (unsigned)((mycol * HCOLW + pw_idx(myk)) << 2);

    for (int step = 0; step < 512; step++) {
        int ph = step & 1;
        s_x[t] = xv0;
        s_x[t + 512] = xv1;
        if (step < 511) { xp0 += 1024; xv0 = *xp0; xp1 += 1024; xv1 = *xp1; }

        float e[4] = {0.f, 0.f, 0.f, 0.f};
        float o[4] = {0.f, 0.f, 0.f, 0.f};
        const ull* hw64 = (const ull*)(s_h + ph * 8 * HCOLW + g * HCOLW);
#pragma unroll
        for (int kt = 0; kt < 8; kt++) {
            ull v = hw64[4 * (8 * kh + kt) + t4];
            unsigned blo = (unsigned)v, bhi = (unsigned)(v >> 32);
            mma16816(e, areg0[4 * kt], areg0[4 * kt + 1], areg0[4 * kt + 2], areg0[4 * kt + 3], blo, bhi);
            mma16816(o, areg1[4 * kt], areg1[4 * kt + 1], areg1[4 * kt + 2], areg1[4 * kt + 3], blo, bhi);
        }
        if (t4 < 2) {
            float* zb = s_z + kh * (4 * SZS);
            int cb = 2 * t4;
            zb[cb * SZS + r1]       = e[0];
            zb[(cb + 1) * SZS + r1] = e[1];
            zb[cb * SZS + r2]       = e[2];
            zb[(cb + 1) * SZS + r2] = e[3];
            zb[cb * SZS + r3]       = o[0];
            zb[(cb + 1) * SZS + r3] = o[1];
            zb[cb * SZS + r4]       = o[2];
            zb[(cb + 1) * SZS + r4] = o[3];
        }
        __syncthreads();
        unsigned mbq = mb_sh + (unsigned)((step & 1) << 3);
        if (t < 256) {
            const float* z0 = s_z + mycol * SZS;
            const float* z1 = s_z + 4 * SZS + mycol * SZS;
            const float* x = s_x + mycol * 256;
            float zi = z0[myu]       + z1[myu]       + x[myu];
            float zf = z0[64 + myu]  + z1[64 + myu]  + x[64 + myu];
            float zg = z0[128 + myu] + z1[128 + myu] + x[128 + myu];
            float zo = z0[192 + myu] + z1[192 + myu] + x[192 + myu];
            float cc = sigf(zf) * s_c[t] + sigf(zi) * tanhf(zg);
            float hh = sigf(zo) * tanhf(cc);
            s_c[t] = cc;
            u16 h16 = f2b(hh);
            if (step < 511)
                g_hdec_bf[((size_t)myb * ND + step + 1) * HH + myk] = h16;
            unsigned pn = __shfl_down_sync(0xffffffffu, (unsigned)h16, 1);
            if (!(myu & 1)) {
                unsigned pk = (unsigned)h16 | (pn << 16);
                unsigned off = h_sh + (unsigned)((ph ^ 1) * 8 * HCOLW * 4) + stcol;
                st_peer32(off, 0, pk);
                st_peer32(off, 1, pk);
                st_peer32(off, 2, pk);
                st_peer32(off, 3, pk);
            }
            __syncwarp();
            if (lane == 0) {
                mbar_arrive_peer(mbq, 0);
                mbar_arrive_peer(mbq, 1);
                mbar_arrive_peer(mbq, 2);
                mbar_arrive_peer(mbq, 3);
            }
        }
        mbar_wait_parity(mbq, (unsigned)((step >> 1) & 1));
    }
    CLUSTER_BAR();
}

// ---------------- alignment softmax + score mix ----------------
__global__ void k_align()
{
    int bj = blockIdx.x;
    const float* E = g_E + (size_t)bj * NE;
    const float* S = g_S + (size_t)bj * NE;
    int t = threadIdx.x;
    __shared__ float r1[256];
    __shared__ float r2[256];

    float m = -1e30f;
    for (int i = t; i < NE; i += 256) m = fmaxf(m, E[i]);
    r1[t] = m; __syncthreads();
    for (int s = 128; s > 0; s >>= 1) { if (t < s) r1[t] = fmaxf(r1[t], r1[t + s]); __syncthreads(); }
    m = r1[0];
    __syncthreads();

    float s1 = 0.f, s2 = 0.f;
    for (int i = t; i < NE; i += 256) {
        float e = expf(E[i] - m);
        s1 += e;
        s2 += e * S[i];
    }
    r1[t] = s1; r2[t] = s2; __syncthreads();
    for (int s = 128; s > 0; s >>= 1) {
        if (t < s) { r1[t] += r1[t + s]; r2[t] += r2[t + s]; }
        __syncthreads();
    }
    if (t == 0) g_p[bj] = logf(r2[0]) - logf(r1[0]);
}

__global__ void k_final(float* __restrict__ out)
{
    int t = threadIdx.x;
    __shared__ float red[1024];
    float s = 0.f;
    for (int i = t; i < BB * ND; i += 1024) s += g_p[i];
    red[t] = s; __syncthreads();
    for (int sr = 512; sr > 0; sr >>= 1) { if (t < sr) red[t] += red[t + sr]; __syncthreads(); }
    if (t == 0) out[0] = -red[0];
}

// ---------------- host launcher ----------------
extern "C" void kernel_launch(void* const* d_in, const int* in_sizes, int n_in,
                              void* d_out, int out_size)
{
    const int*   xs        = (const int*)d_in[0];
    const int*   ys        = (const int*)d_in[1];
    const float* gembed    = (const float*)d_in[2];
    const float* gconv     = (const float*)d_in[3];
    const float* gdecode   = (const float*)d_in[4];
    const float* enc_embed = (const float*)d_in[5];
    const float* dec_embed = (const float*)d_in[6];
    const float* enc_Wih   = (const float*)d_in[7];
    const float* enc_Whh   = (const float*)d_in[8];
    const float* enc_b     = (const float*)d_in[9];
    const float* dec_Wih   = (const float*)d_in[10];
    const float* dec_Whh   = (const float*)d_in[11];
    const float* dec_b     = (const float*)d_in[12];
    const float* Tm        = (const float*)d_in[13];

    u16 *p_epad, *p_t, *p_xemb, *p_yemb, *p_gconv, *p_gdec, *p_wE, *p_wD, *p_Tb;
    u16 *p_hcat, *p_hdec, *p_Th;
    float *p_logits, *p_xz, *p_yz, *p_E;
    cudaGetSymbolAddress((void**)&p_epad, g_epad_bf);
    cudaGetSymbolAddress((void**)&p_t, g_t_bf);
    cudaGetSymbolAddress((void**)&p_xemb, g_xemb_bf);
    cudaGetSymbolAddress((void**)&p_yemb, g_yemb_bf);
    cudaGetSymbolAddress((void**)&p_gconv, g_gconv_bf);
    cudaGetSymbolAddress((void**)&p_gdec, g_gdec_bf);
    cudaGetSymbolAddress((void**)&p_wE, g_wihE_bf);
    cudaGetSymbolAddress((void**)&p_wD, g_wihD_bf);
    cudaGetSymbolAddress((void**)&p_Tb, g_T_bf);
    cudaGetSymbolAddress((void**)&p_hcat, g_hcat_bf);
    cudaGetSymbolAddress((void**)&p_hdec, g_hdec_bf);
    cudaGetSymbolAddress((void**)&p_Th, g_Th_bf);
    cudaGetSymbolAddress((void**)&p_logits, g_logits);
    cudaGetSymbolAddress((void**)&p_xz, g_xz);
    cudaGetSymbolAddress((void**)&p_yz, g_yz);
    cudaGetSymbolAddress((void**)&p_E, g_E);

    static cudaStream_t s1 = nullptr, s2 = nullptr, s3 = nullptr;
    static cudaEvent_t eMain = nullptr, eg = nullptr, eFwd = nullptr, eBwd = nullptr;
    static cudaEvent_t eth = nullptr, eYZ = nullptr;
    static bool init_done = false;
    if (!init_done) {
        int prLo = 0, prHi = 0;
        cudaDeviceGetStreamPriorityRange(&prLo, &prHi);
        cudaStreamCreateWithPriority(&s1, cudaStreamNonBlocking, prLo);
        cudaStreamCreateWithPriority(&s2, cudaStreamNonBlocking, prHi);
        cudaStreamCreateWithPriority(&s3, cudaStreamNonBlocking, prHi);
        cudaEventCreateWithFlags(&eMain, cudaEventDisableTiming);
        cudaEventCreateWithFlags(&eg, cudaEventDisableTiming);
        cudaEventCreateWithFlags(&eFwd, cudaEventDisableTiming);
        cudaEventCreateWithFlags(&eBwd, cudaEventDisableTiming);
        cudaEventCreateWithFlags(&eth, cudaEventDisableTiming);
        cudaEventCreateWithFlags(&eYZ, cudaEventDisableTiming);
        init_done = true;
    }

    // ---- main stream: minimal critical-path prep (pack, emb, xz) ----
    k_pack<<<128, 256>>>(enc_Whh, dec_Whh);
    k_emb<<<(BB * NE * EE + 255) / 256, 256>>>(xs, ys, enc_embed, dec_embed);
    hgemm<2, true><<<dim3(8, 128, 1), 256>>>(p_xemb, 0, EE,
                                             p_wE, 0, EE,
                                             p_xz, 0, 4 * HH,
                                             BB * NE, 4 * HH, EE, enc_b);
    cudaEventRecord(eMain, 0);

    // ---- backward encoder on s3, forward encoder on main (concurrent) ----
    cudaStreamWaitEvent(s3, eMain, 0);
    lstm_dir_mma<1><<<32, 512, 0, s3>>>();
    cudaEventRecord(eBwd, s3);

    lstm_dir_mma<0><<<32, 512>>>();
    cudaEventRecord(eFwd, 0);

    // ---- s1 (low prio): yz first (needed by dec), then G-equivariant chain ----
    cudaStreamWaitEvent(s1, eMain, 0);
    hgemm<2, true><<<dim3(8, 128, 1), 256, 0, s1>>>(p_yemb, 0, EE,
                                                    p_wD, 0, EE,
                                                    p_yz, 0, 4 * HH,
                                                    BB * ND, 4 * HH, EE, dec_b);
    cudaEventRecord(eYZ, s1);
    k_cvt<<<(FF * VOC + 255) / 256, 256, 0, s1>>>(gconv, gdecode, enc_Wih, dec_Wih, Tm);
    k_epad<<<(BB * 516 * FF + 255) / 256, 256, 0, s1>>>(xs, gembed);
    hgemm<1, false><<<dim3(2, 4, BB), 256, 0, s1>>>(p_epad, (size_t)516 * FF, FF,
                                                    p_gconv, 0, FF,
                                                    p_t, (size_t)NE * FF, FF,
                                                    NE, FF, 5 * FF, nullptr);
    hgemm<0, false><<<dim3(16, 128, 1), 256, 0, s1>>>(p_t, 0, FF,
                                                      p_gdec, 0, VOC,
                                                      p_logits, 0, VOC,
                                                      BB * NE, VOC, FF, nullptr);
    k_rowstats<<<BB * NE, 256, 0, s1>>>();
    k_scores<<<BB * ND, 512, 0, s1>>>(ys);
    cudaEventRecord(eg, s1);

    // Th = h_enc @ T^T — needs fwd + bwd; overlaps lstm_dec on s2
    cudaStreamWaitEvent(s2, eFwd, 0);
    cudaStreamWaitEvent(s2, eBwd, 0);
    hgemm<3, true><<<dim3(2, 4, BB), 256, 0, s2>>>(p_hcat, (size_t)NE * 2 * HH, 2 * HH,
                                                   p_Tb, 0, 2 * HH,
                                                   p_Th, (size_t)NE * HH, HH,
                                                   NE, HH, 2 * HH, nullptr);
    cudaEventRecord(eth, s2);

    // ---- decoder (needs fwd via stream order + yz) ----
    cudaStreamWaitEvent(0, eYZ, 0);
    lstm_dec_mma<<<32, 512>>>();

    // E[b][j][i] = h_dec[b][j] . Th[b][i]
    cudaStreamWaitEvent(0, eth, 0);
    hgemm<0, true><<<dim3(4, 4, BB), 256>>>(p_hdec, (size_t)ND * HH, HH,
                                            p_Th, (size_t)NE * HH, HH,
                                            p_E, (size_t)ND * NE, NE,
                                            ND, NE, HH, nullptr);

    cudaStreamWaitEvent(0, eg, 0);
    k_align<<<BB * ND, 256>>>();
    k_final<<<1, 1024>>>((float*)d_out);
}

// round 15
// speedup vs baseline: 2.1109x; 2.1109x over previous
#include <cuda_runtime.h>
#include <cuda_bf16.h>
#include <cstdint>
#include <cstddef>

typedef unsigned long long ull;
typedef unsigned short u16;

// Problem constants
#define BB   32
#define NE   512
#define ND   512
#define VOC  2000
#define HH   256
#define FF   256
#define PP   4
#define EE   128

// ---------------- scratch (device globals; no allocations allowed) ----------------
__device__ __align__(16) u16 g_epad_bf[(size_t)BB * 516 * FF];
__device__ __align__(16) u16 g_t_bf[(size_t)BB * NE * FF];
__device__ float g_logits[(size_t)BB * NE * VOC];
__device__ float g_rmax[BB * NE];
__device__ float g_rsum[BB * NE];
__device__ float g_S[(size_t)BB * ND * NE];               // (b, j, i)
__device__ __align__(16) u16 g_xemb_bf[(size_t)BB * NE * EE];
__device__ __align__(16) u16 g_yemb_bf[(size_t)BB * ND * EE];
__device__ float g_xz[(size_t)BB * NE * 4 * HH];
__device__ float g_yz[(size_t)BB * ND * 4 * HH];
__device__ __align__(16) uint4 g_WencP4[32 * 1024];       // Whh bf16x2, [kk][row]
__device__ __align__(16) uint4 g_WdecP4[32 * 1024];
__device__ __align__(16) u16 g_gconv_bf[5 * FF * FF];     // 1280 x 256
__device__ __align__(16) u16 g_gdec_bf[FF * VOC];         // 256 x 2000
__device__ __align__(16) u16 g_wihE_bf[4 * HH * EE];      // 1024 x 128
__device__ __align__(16) u16 g_wihD_bf[4 * HH * EE];
__device__ __align__(16) u16 g_T_bf[HH * 2 * HH];         // 256 x 512
__device__ __align__(16) u16 g_hcat_bf[(size_t)BB * NE * 2 * HH];
__device__ float g_cT[BB * HH];
__device__ __align__(16) u16 g_hdec_bf[(size_t)BB * ND * HH];
__device__ __align__(16) u16 g_Th_bf[(size_t)BB * NE * HH];
__device__ float g_E[(size_t)BB * ND * NE];               // (b, j, i)
__device__ float g_p[BB * ND];

// ---------------- common helpers ----------------
__device__ __forceinline__ float sigf(float x) { return 1.f / (1.f + expf(-x)); }
__device__ __forceinline__ unsigned smem_u32(const void* p)
{
    unsigned a;
    asm("{ .reg .u64 t; cvta.to.shared.u64 t, %1; cvt.u32.u64 %0, t; }" : "=r"(a) : "l"(p));
    return a;
}
__device__ __forceinline__ void mma16816(float* c,
                                         unsigned a0, unsigned a1, unsigned a2, unsigned a3,
                                         unsigned b0, unsigned b1)
{
    asm("mma.sync.aligned.m16n8k16.row.col.f32.bf16.bf16.f32 "
        "{%0,%1,%2,%3}, {%4,%5,%6,%7}, {%8,%9}, {%0,%1,%2,%3};"
        : "+f"(c[0]), "+f"(c[1]), "+f"(c[2]), "+f"(c[3])
        : "r"(a0), "r"(a1), "r"(a2), "r"(a3), "r"(b0), "r"(b1));
}
__device__ __forceinline__ void ldsm4(unsigned& r0, unsigned& r1, unsigned& r2, unsigned& r3,
                                      unsigned addr)
{
    asm volatile("ldmatrix.sync.aligned.m8n8.x4.shared.b16 {%0,%1,%2,%3}, [%4];"
                 : "=r"(r0), "=r"(r1), "=r"(r2), "=r"(r3) : "r"(addr));
}
__device__ __forceinline__ void ldsm4t(unsigned& r0, unsigned& r1, unsigned& r2, unsigned& r3,
                                       unsigned addr)
{
    asm volatile("ldmatrix.sync.aligned.m8n8.x4.trans.shared.b16 {%0,%1,%2,%3}, [%4];"
                 : "=r"(r0), "=r"(r1), "=r"(r2), "=r"(r3) : "r"(addr));
}

// ---------------- bf16 tensor-core GEMM (unchanged R8/R9 winner) ----------------
template <int EPI, bool TB>
__global__ void __launch_bounds__(256) hgemm(
    const u16* __restrict__ A, size_t sAz, int lda,
    const u16* __restrict__ B, size_t sBz, int ldb,
    void* __restrict__ C, size_t sCz, int ldc,
    int M, int N, int K, const float* __restrict__ bias)
{
    __shared__ __align__(16) char smem[20480];
    char* smA = smem;
    char* smB = smem + 10240;

    const u16* Ab = A + blockIdx.z * sAz;
    const u16* Bb = B + blockIdx.z * sBz;

    const int bm0 = blockIdx.y * 128;
    const int bn0 = blockIdx.x * 128;
    const int tid = threadIdx.x;
    const int w = tid >> 5, lane = tid & 31;
    const int wm = w >> 1, wn = w & 1;
    const int sel = lane >> 3, lr = lane & 7;

    float acc[2][8][4];
#pragma unroll
    for (int mi = 0; mi < 2; mi++)
#pragma unroll
        for (int nf = 0; nf < 8; nf++)
#pragma unroll
            for (int i = 0; i < 4; i++) acc[mi][nf][i] = 0.f;

    unsigned aA = smem_u32(smA);
    unsigned aB = aA + 10240;

    const int arow = wm * 32 + lr + (sel & 1) * 8;
    const int aksl = (sel >> 1) * 8;
    const int ntrow = wn * 64 + lr + (sel >> 1) * 8;
    const int ntksl = (sel & 1) * 8;
    const int nnksl = lr + (sel & 1) * 8;
    const int nnnof = wn * 64 + (sel >> 1) * 8;

    for (int k0 = 0; k0 < K; k0 += 32) {
#pragma unroll
        for (int j = 0; j < 2; j++) {
            int idx = tid + 256 * j;
            int row = idx >> 2, grp = idx & 3;
            uint4 v = *(const uint4*)(Ab + (size_t)(bm0 + row) * lda + k0 + grp * 8);
            *(uint4*)(smA + row * 80 + grp * 16) = v;
        }
        if (TB) {
#pragma unroll
            for (int j = 0; j < 2; j++) {
                int idx = tid + 256 * j;
                int row = idx >> 2, grp = idx & 3;
                uint4 v = *(const uint4*)(Bb + (size_t)(bn0 + row) * ldb + k0 + grp * 8);
                *(uint4*)(smB + row * 80 + grp * 16) = v;
            }
        } else {
#pragma unroll
            for (int j = 0; j < 2; j++) {
                int idx = tid + 256 * j;
                int k = idx >> 4, ngrp = idx & 15;
                int n0c = bn0 + ngrp * 8;
                uint4 v = make_uint4(0u, 0u, 0u, 0u);
                if (n0c + 8 <= N) v = *(const uint4*)(Bb + (size_t)(k0 + k) * ldb + n0c);
                *(uint4*)(smB + k * 272 + ngrp * 16) = v;
            }
        }
        __syncthreads();

#pragma unroll
        for (int q = 0; q < 32; q += 16) {
            unsigned a[2][4];
#pragma unroll
            for (int mi = 0; mi < 2; mi++)
                ldsm4(a[mi][0], a[mi][1], a[mi][2], a[mi][3],
                      aA + (unsigned)((arow + mi * 16) * 80 + (q + aksl) * 2));
#pragma unroll
            for (int nf2 = 0; nf2 < 4; nf2++) {
                unsigned b0, b1, b2, b3;
                if (TB) {
                    ldsm4(b0, b1, b2, b3,
                          aB + (unsigned)((ntrow + nf2 * 16) * 80 + (q + ntksl) * 2));
                } else {
                    ldsm4t(b0, b1, b2, b3,
                           aB + (unsigned)((q + nnksl) * 272 + (nnnof + nf2 * 16) * 2));
                }
#pragma unroll
                for (int mi = 0; mi < 2; mi++) {
                    mma16816(acc[mi][2 * nf2], a[mi][0], a[mi][1], a[mi][2], a[mi][3], b0, b1);
                    mma16816(acc[mi][2 * nf2 + 1], a[mi][0], a[mi][1], a[mi][2], a[mi][3], b2, b3);
                }
            }
        }
        __syncthreads();
    }

    const int er = bm0 + wm * 32 + (lane >> 2);
    const int ec = bn0 + wn * 64 + (lane & 3) * 2;
#pragma unroll
    for (int mi = 0; mi < 2; mi++) {
#pragma unroll
        for (int nf = 0; nf < 8; nf++) {
            int col = ec + nf * 8;
            if (col >= N) continue;
#pragma unroll
            for (int half = 0; half < 2; half++) {
                int row = er + mi * 16 + half * 8;
                float v0 = acc[mi][nf][2 * half];
                float v1 = acc[mi][nf][2 * half + 1];
                if (EPI == 0) {
                    float2 o = make_float2(v0, v1);
                    *(float2*)((float*)C + (size_t)blockIdx.z * sCz + (size_t)row * ldc + col) = o;
                } else if (EPI == 2) {
                    float2 o = make_float2(v0 + bias[col], v1 + bias[col + 1]);
                    *(float2*)((float*)C + (size_t)blockIdx.z * sCz + (size_t)row * ldc + col) = o;
                } else {
                    float w0 = (EPI == 1) ? tanhf(v0) : v0;
                    float w1 = (EPI == 1) ? tanhf(v1) : v1;
                    __nv_bfloat162 o = __floats2bfloat162_rn(w0, w1);
                    *(__nv_bfloat162*)((u16*)C + (size_t)blockIdx.z * sCz + (size_t)row * ldc + col) = o;
                }
            }
        }
    }
}

// ---------------- prep kernels ----------------
__device__ __forceinline__ u16 f2b(float x) { return __bfloat16_as_ushort(__float2bfloat16(x)); }

__global__ void k_epad(const int* __restrict__ xs, const float* __restrict__ gembed)
{
    int idx = blockIdx.x * 256 + threadIdx.x;
    if (idx >= BB * 516 * FF) return;
    int f = idx & 255;
    int rest = idx >> 8;
    int ip = rest % 516;
    int b = rest / 516;
    float v = 0.f;
    int i = ip - 2;
    if (i >= 0 && i < NE) {
        int id = xs[b * NE + i];
        v = tanhf(gembed[(size_t)id * FF + f]);
    }
    g_epad_bf[idx] = f2b(v);
}

__global__ void k_emb(const int* __restrict__ xs, const int* __restrict__ ys,
                      const float* __restrict__ enc_e, const float* __restrict__ dec_e)
{
    int idx = blockIdx.x * 256 + threadIdx.x;
    if (idx >= BB * NE * EE) return;
    int f = idx & 127;
    int r = idx >> 7;
    int xi = xs[r]; if (xi < PP) xi = 0;
    g_xemb_bf[idx] = f2b(enc_e[(size_t)xi * EE + f]);
    int yi = ys[r]; if (yi < PP) yi = 0;
    g_yemb_bf[idx] = f2b(dec_e[(size_t)yi * EE + f]);
}

__global__ void k_cvt(const float* __restrict__ gconv, const float* __restrict__ gdec,
                      const float* __restrict__ wE, const float* __restrict__ wD,
                      const float* __restrict__ T)
{
    int i = blockIdx.x * 256 + threadIdx.x;
    if (i < 5 * FF * FF) g_gconv_bf[i] = f2b(gconv[i]);
    if (i < FF * VOC)    g_gdec_bf[i]  = f2b(gdec[i]);
    if (i < 4 * HH * EE) { g_wihE_bf[i] = f2b(wE[i]); g_wihD_bf[i] = f2b(wD[i]); }
    if (i < HH * 2 * HH) g_T_bf[i] = f2b(T[i]);
}

__device__ __forceinline__ unsigned pack_bf2(float a, float b)
{
    return (unsigned)f2b(a) | ((unsigned)f2b(b) << 16);
}

__global__ void k_pack(const float* __restrict__ We, const float* __restrict__ Wd)
{
    int idx = blockIdx.x * 256 + threadIdx.x;
    if (idx >= 32 * 1024) return;
    int kk = idx >> 10, n = idx & 1023;
    const float* re = We + (size_t)n * 256 + 8 * kk;
    const float* rd = Wd + (size_t)n * 256 + 8 * kk;
    uint4 ve, vd;
    ve.x = pack_bf2(re[0], re[1]); ve.y = pack_bf2(re[2], re[3]);
    ve.z = pack_bf2(re[4], re[5]); ve.w = pack_bf2(re[6], re[7]);
    vd.x = pack_bf2(rd[0], rd[1]); vd.y = pack_bf2(rd[2], rd[3]);
    vd.z = pack_bf2(rd[4], rd[5]); vd.w = pack_bf2(rd[6], rd[7]);
    g_WencP4[idx] = ve;
    g_WdecP4[idx] = vd;
}

// ---------------- softmax row stats over vocab ----------------
__global__ void k_rowstats()
{
    int row = blockIdx.x;
    const float* L = g_logits + (size_t)row * VOC;
    int t = threadIdx.x;
    __shared__ float red[256];
    float m = -1e30f;
    for (int v = t; v < VOC; v += 256) m = fmaxf(m, L[v]);
    red[t] = m; __syncthreads();
    for (int s = 128; s > 0; s >>= 1) { if (t < s) red[t] = fmaxf(red[t], red[t + s]); __syncthreads(); }
    m = red[0];
    __syncthreads();
    float s = 0.f;
    for (int v = t; v < VOC; v += 256) s += expf(L[v] - m);
    red[t] = s; __syncthreads();
    for (int sr = 128; sr > 0; sr >>= 1) { if (t < sr) red[t] += red[t + sr]; __syncthreads(); }
    if (t == 0) { g_rmax[row] = m; g_rsum[row] = red[0]; }
}

__global__ void k_scores(const int* __restrict__ ys)
{
    int bj = blockIdx.x;
    int b = bj >> 9;
    int v = ys[bj];
    int i = threadIdx.x;
    size_t row = (size_t)b * NE + i;
    float l = g_logits[row * VOC + v];
    g_S[(size_t)bj * NE + i] = expf(l - g_rmax[row]) / g_rsum[row];
}

// ---------------- LSTM: mma.sync, reg-stationary W, cluster.bar sync ----------------
#define CLUSTER_BAR() do { \
    asm volatile("barrier.cluster.arrive.aligned;" ::: "memory"); \
    asm volatile("barrier.cluster.wait.aligned;" ::: "memory"); } while (0)

__device__ __forceinline__ void st_peer32(unsigned off, int rank, unsigned v)
{
    unsigned ra;
    asm volatile("mapa.shared::cluster.u32 %0, %1, %2;" : "=r"(ra) : "r"(off), "r"(rank));
    asm volatile("st.shared::cluster.b32 [%0], %1;" :: "r"(ra), "r"(v) : "memory");
}

#define HCOLW 136   // words per h column; paired layout, conflict-free LDS.64
#define SZS   260   // s_z column stride (floats)

// paired word index for hidden unit k: word holds (h[k&~1], h[k|1])
__device__ __forceinline__ int pw_idx(int k)
{
    int w = (k >> 1) & 7;
    return (k >> 4) * 8 + (w & 3) * 2 + (w >> 2);
}

// Single-direction encoder pass. DIR=0 forward (also writes g_cT at final step),
// DIR=1 backward. 8 clusters x 4 CTAs (grid 32). Cluster = 4 batches (cols 0..3).
// Warp w: m-block mb=w&7 (32 local rows), k-half kh=w>>3.
template <int DIR>
__global__ void __launch_bounds__(512, 1) __cluster_dims__(4, 1, 1) lstm_dir_mma()
{
    __shared__ __align__(16) unsigned s_h[2 * 8 * HCOLW];
    __shared__ float s_x[1024];
    __shared__ float s_z[8 * SZS];
    __shared__ float s_c[256];

    unsigned rank; asm("mov.u32 %0, %%cluster_ctarank;" : "=r"(rank));
    int cl = blockIdx.x >> 2;
    int t = threadIdx.x;
    int w = t >> 5, lane = t & 31, g = lane >> 2, t4 = lane & 3;
    int mb = w & 7, kh = w >> 3;
    int r1 = 32 * mb + g, r2 = r1 + 8, r3 = r1 + 16, r4 = r1 + 24;
    int R1 = ((r1 >> 6) << 8) + (int)(rank << 6) + (r1 & 63);
    int R2 = ((r2 >> 6) << 8) + (int)(rank << 6) + (r2 & 63);
    int R3 = ((r3 >> 6) << 8) + (int)(rank << 6) + (r3 & 63);
    int R4 = ((r4 >> 6) << 8) + (int)(rank << 6) + (r4 & 63);

    unsigned areg0[32], areg1[32];
    const unsigned* WP = (const unsigned*)g_WencP4;
#pragma unroll
    for (int kt = 0; kt < 8; kt++) {
        int j = 8 * kh + kt;
        areg0[4 * kt + 0] = WP[(((2 * j) * 1024 + R1) << 2) + t4];
        areg0[4 * kt + 1] = WP[(((2 * j) * 1024 + R2) << 2) + t4];
        areg0[4 * kt + 2] = WP[(((2 * j + 1) * 1024 + R1) << 2) + t4];
        areg0[4 * kt + 3] = WP[(((2 * j + 1) * 1024 + R2) << 2) + t4];
        areg1[4 * kt + 0] = WP[(((2 * j) * 1024 + R3) << 2) + t4];
        areg1[4 * kt + 1] = WP[(((2 * j) * 1024 + R4) << 2) + t4];
        areg1[4 * kt + 2] = WP[(((2 * j + 1) * 1024 + R3) << 2) + t4];
        areg1[4 * kt + 3] = WP[(((2 * j + 1) * 1024 + R4) << 2) + t4];
    }

    // x prefetch: two streams per thread, TWO steps deep
    int c0i = t >> 8, row0 = t & 255;
    int c1i = (t + 512) >> 8;
    int b0i = 4 * cl + c0i, b1i = 4 * cl + c1i;
    int Gr0 = ((row0 >> 6) << 8) + (int)(rank << 6) + (row0 & 63);
    const float* xp0 = g_xz + ((size_t)b0i * NE + (DIR ? 511 : 0)) * 1024 + Gr0;
    const float* xp1 = g_xz + ((size_t)b1i * NE + (DIR ? 511 : 0)) * 1024 + Gr0;
    const int xstride = DIR ? -1024 : 1024;
    float xv0 = xp0[0], xv1 = xp1[0];
    float xn0 = xp0[xstride], xn1 = xp1[xstride];

    for (int i = t; i < 2 * 8 * HCOLW; i += 512) s_h[i] = 0;
    if (t < 256) s_c[t] = 0.f;
    __syncthreads();
    CLUSTER_BAR();

    unsigned h_sh = smem_u32(s_h);

    int mycol = t >> 6, myu = t & 63;
    int myb = 4 * cl + mycol;
    int myk = (int)(rank << 6) + myu;
    unsigned stcol = (unsigned)((mycol * HCOLW + pw_idx(myk)) << 2);

    for (int step = 0; step < 512; step++) {
        int ph = step & 1;
        int tt = DIR ? (511 - step) : step;

        s_x[t] = xv0;
        s_x[t + 512] = xv1;
        float xf0 = xn0, xf1 = xn1;
        if (step < 510) { xf0 = xp0[2 * xstride]; xf1 = xp1[2 * xstride]; }
        xp0 += xstride; xp1 += xstride;

        float e[4] = {0.f, 0.f, 0.f, 0.f};
        float o[4] = {0.f, 0.f, 0.f, 0.f};
        const ull* hw64 = (const ull*)(s_h + ph * 8 * HCOLW + g * HCOLW);
#pragma unroll
        for (int kt = 0; kt < 8; kt++) {
            ull v = hw64[4 * (8 * kh + kt) + t4];
            unsigned blo = (unsigned)v, bhi = (unsigned)(v >> 32);
            mma16816(e, areg0[4 * kt], areg0[4 * kt + 1], areg0[4 * kt + 2], areg0[4 * kt + 3], blo, bhi);
            mma16816(o, areg1[4 * kt], areg1[4 * kt + 1], areg1[4 * kt + 2], areg1[4 * kt + 3], blo, bhi);
        }
        if (t4 < 2) {
            float* zb = s_z + kh * (4 * SZS);
            int cb = 2 * t4;
            zb[cb * SZS + r1]       = e[0];
            zb[(cb + 1) * SZS + r1] = e[1];
            zb[cb * SZS + r2]       = e[2];
            zb[(cb + 1) * SZS + r2] = e[3];
            zb[cb * SZS + r3]       = o[0];
            zb[(cb + 1) * SZS + r3] = o[1];
            zb[cb * SZS + r4]       = o[2];
            zb[(cb + 1) * SZS + r4] = o[3];
        }
        __syncthreads();
        if (t < 256) {
            const float* z0 = s_z + mycol * SZS;
            const float* z1 = s_z + 4 * SZS + mycol * SZS;
            const float* x = s_x + mycol * 256;
            float zi = z0[myu]       + z1[myu]       + x[myu];
            float zf = z0[64 + myu]  + z1[64 + myu]  + x[64 + myu];
            float zg = z0[128 + myu] + z1[128 + myu] + x[128 + myu];
            float zo = z0[192 + myu] + z1[192 + myu] + x[192 + myu];
            float cc = sigf(zf) * s_c[t] + sigf(zi) * tanhf(zg);
            float hh = sigf(zo) * tanhf(cc);
            s_c[t] = cc;
            u16 h16 = f2b(hh);
            g_hcat_bf[((size_t)myb * NE + tt) * 512 + DIR * 256 + myk] = h16;
            if (DIR == 0 && step == 511) g_cT[myb * 256 + myk] = cc;
            unsigned pn = __shfl_down_sync(0xffffffffu, (unsigned)h16, 1);
            if (!(myu & 1)) {
                unsigned pk = (unsigned)h16 | (pn << 16);
                unsigned off = h_sh + (unsigned)((ph ^ 1) * 8 * HCOLW * 4) + stcol;
                st_peer32(off, 0, pk);
                st_peer32(off, 1, pk);
                st_peer32(off, 2, pk);
                st_peer32(off, 3, pk);
            }
        }
        xv0 = xn0; xv1 = xn1;
        xn0 = xf0; xn1 = xf1;
        CLUSTER_BAR();
    }
}

// Decoder: 8 clusters x 4 CTAs (grid 32). Cluster = 4 batches (cols 0..3).
__global__ void __launch_bounds__(512, 1) __cluster_dims__(4, 1, 1) lstm_dec_mma()
{
    __shared__ __align__(16) unsigned s_h[2 * 8 * HCOLW];
    __shared__ float s_x[1024];
    __shared__ float s_z[8 * SZS];
    __shared__ float s_c[256];

    unsigned rank; asm("mov.u32 %0, %%cluster_ctarank;" : "=r"(rank));
    int cl = blockIdx.x >> 2;
    int t = threadIdx.x;
    int w = t >> 5, lane = t & 31, g = lane >> 2, t4 = lane & 3;
    int mb = w & 7, kh = w >> 3;
    int r1 = 32 * mb + g, r2 = r1 + 8, r3 = r1 + 16, r4 = r1 + 24;
    int R1 = ((r1 >> 6) << 8) + (int)(rank << 6) + (r1 & 63);
    int R2 = ((r2 >> 6) << 8) + (int)(rank << 6) + (r2 & 63);
    int R3 = ((r3 >> 6) << 8) + (int)(rank << 6) + (r3 & 63);
    int R4 = ((r4 >> 6) << 8) + (int)(rank << 6) + (r4 & 63);

    unsigned areg0[32], areg1[32];
    const unsigned* WP = (const unsigned*)g_WdecP4;
#pragma unroll
    for (int kt = 0; kt < 8; kt++) {
        int j = 8 * kh + kt;
        areg0[4 * kt + 0] = WP[(((2 * j) * 1024 + R1) << 2) + t4];
        areg0[4 * kt + 1] = WP[(((2 * j) * 1024 + R2) << 2) + t4];
        areg0[4 * kt + 2] = WP[(((2 * j + 1) * 1024 + R1) << 2) + t4];
        areg0[4 * kt + 3] = WP[(((2 * j + 1) * 1024 + R2) << 2) + t4];
        areg1[4 * kt + 0] = WP[(((2 * j) * 1024 + R3) << 2) + t4];
        areg1[4 * kt + 1] = WP[(((2 * j) * 1024 + R4) << 2) + t4];
        areg1[4 * kt + 2] = WP[(((2 * j + 1) * 1024 + R3) << 2) + t4];
        areg1[4 * kt + 3] = WP[(((2 * j + 1) * 1024 + R4) << 2) + t4];
    }

    // x prefetch, two steps deep
    int c0i = t >> 8, row0 = t & 255;
    int c1i = (t + 512) >> 8;
    int b0i = 4 * cl + c0i, b1i = 4 * cl + c1i;
    int Gr0 = ((row0 >> 6) << 8) + (int)(rank << 6) + (row0 & 63);
    const float* xp0 = g_yz + (size_t)b0i * ND * 1024 + Gr0;
    const float* xp1 = g_yz + (size_t)b1i * ND * 1024 + Gr0;
    float xv0 = xp0[0], xv1 = xp1[0];
    float xn0 = xp0[1024], xn1 = xp1[1024];

    for (int i = t; i < 2 * 8 * HCOLW; i += 512) s_h[i] = 0;
    __syncthreads();
    // init h0 (paired layout, buf0 cols 0..3), hdec[:,0], c0
    for (int idx = t; idx < 1024; idx += 512) {
        int col = idx >> 8, k = idx & 255;
        int b = 4 * cl + col;
        u16 hb = g_hcat_bf[((size_t)b * NE + 511) * 512 + k];
        ((u16*)s_h)[(col * HCOLW + pw_idx(k)) * 2 + (k & 1)] = hb;
        if (rank == 0) g_hdec_bf[(size_t)b * ND * HH + k] = hb;
    }
    if (t < 256) {
        int col = t >> 6, u = t & 63;
        s_c[t] = g_cT[(4 * cl + col) * 256 + (int)(rank << 6) + u];
    }
    __syncthreads();
    CLUSTER_BAR();

    unsigned h_sh = smem_u32(s_h);

    int mycol = t >> 6, myu = t & 63;
    int myb = 4 * cl + mycol;
    int myk = (int)(rank << 6) + myu;
    unsigned stcol = (unsigned)((mycol * HCOLW + pw_idx(myk)) << 2);

    for (int step = 0; step < 512; step++) {
        int ph = step & 1;
        s_x[t] = xv0;
        s_x[t + 512] = xv1;
        float xf0 = xn0, xf1 = xn1;
        if (step < 510) { xf0 = xp0[2048]; xf1 = xp1[2048]; }
        xp0 += 1024; xp1 += 1024;

        float e[4] = {0.f, 0.f, 0.f, 0.f};
        float o[4] = {0.f, 0.f, 0.f, 0.f};
        const ull* hw64 = (const ull*)(s_h + ph * 8 * HCOLW + g * HCOLW);
#pragma unroll
        for (int kt = 0; kt < 8; kt++) {
            ull v = hw64[4 * (8 * kh + kt) + t4];
            unsigned blo = (unsigned)v, bhi = (unsigned)(v >> 32);
            mma16816(e, areg0[4 * kt], areg0[4 * kt + 1], areg0[4 * kt + 2], areg0[4 * kt + 3], blo, bhi);
            mma16816(o, areg1[4 * kt], areg1[4 * kt + 1], areg1[4 * kt + 2], areg1[4 * kt + 3], blo, bhi);
        }
        if (t4 < 2) {
            float* zb = s_z + kh * (4 * SZS);
            int cb = 2 * t4;
            zb[cb * SZS + r1]       = e[0];
            zb[(cb + 1) * SZS + r1] = e[1];
            zb[cb * SZS + r2]       = e[2];
            zb[(cb + 1) * SZS + r2] = e[3];
            zb[cb * SZS + r3]       = o[0];
            zb[(cb + 1) * SZS + r3] = o[1];
            zb[cb * SZS + r4]       = o[2];
            zb[(cb + 1) * SZS + r4] = o[3];
        }
        __syncthreads();
        if (t < 256) {
            const float* z0 = s_z + mycol * SZS;
            const float* z1 = s_z + 4 * SZS + mycol * SZS;
            const float* x = s_x + mycol * 256;
            float zi = z0[myu]       + z1[myu]       + x[myu];
            float zf = z0[64 + myu]  + z1[64 + myu]  + x[64 + myu];
            float zg = z0[128 + myu] + z1[128 + myu] + x[128 + myu];
            float zo = z0[192 + myu] + z1[192 + myu] + x[192 + myu];
            float cc = sigf(zf) * s_c[t] + sigf(zi) * tanhf(zg);
            float hh = sigf(zo) * tanhf(cc);
            s_c[t] = cc;
            u16 h16 = f2b(hh);
            if (step < 511)
                g_hdec_bf[((size_t)myb * ND + step + 1) * HH + myk] = h16;
            unsigned pn = __shfl_down_sync(0xffffffffu, (unsigned)h16, 1);
            if (!(myu & 1)) {
                unsigned pk = (unsigned)h16 | (pn << 16);
                unsigned off = h_sh + (unsigned)((ph ^ 1) * 8 * HCOLW * 4) + stcol;
                st_peer32(off, 0, pk);
                st_peer32(off, 1, pk);
                st_peer32(off, 2, pk);
                st_peer32(off, 3, pk);
            }
        }
        xv0 = xn0; xv1 = xn1;
        xn0 = xf0; xn1 = xf1;
        CLUSTER_BAR();
    }
}

// ---------------- alignment softmax + score mix ----------------
__global__ void k_align()
{
    int bj = blockIdx.x;
    const float* E = g_E + (size_t)bj * NE;
    const float* S = g_S + (size_t)bj * NE;
    int t = threadIdx.x;
    __shared__ float r1[256];
    __shared__ float r2[256];

    float m = -1e30f;
    for (int i = t; i < NE; i += 256) m = fmaxf(m, E[i]);
    r1[t] = m; __syncthreads();
    for (int s = 128; s > 0; s >>= 1) { if (t < s) r1[t] = fmaxf(r1[t], r1[t + s]); __syncthreads(); }
    m = r1[0];
    __syncthreads();

    float s1 = 0.f, s2 = 0.f;
    for (int i = t; i < NE; i += 256) {
        float e = expf(E[i] - m);
        s1 += e;
        s2 += e * S[i];
    }
    r1[t] = s1; r2[t] = s2; __syncthreads();
    for (int s = 128; s > 0; s >>= 1) {
        if (t < s) { r1[t] += r1[t + s]; r2[t] += r2[t + s]; }
        __syncthreads();
    }
    if (t == 0) g_p[bj] = logf(r2[0]) - logf(r1[0]);
}

__global__ void k_final(float* __restrict__ out)
{
    int t = threadIdx.x;
    __shared__ float red[1024];
    float s = 0.f;
    for (int i = t; i < BB * ND; i += 1024) s += g_p[i];
    red[t] = s; __syncthreads();
    for (int sr = 512; sr > 0; sr >>= 1) { if (t < sr) red[t] += red[t + sr]; __syncthreads(); }
    if (t == 0) out[0] = -red[0];
}

// ---------------- host launcher ----------------
extern "C" void kernel_launch(void* const* d_in, const int* in_sizes, int n_in,
                              void* d_out, int out_size)
{
    const int*   xs        = (const int*)d_in[0];
    const int*   ys        = (const int*)d_in[1];
    const float* gembed    = (const float*)d_in[2];
    const float* gconv     = (const float*)d_in[3];
    const float* gdecode   = (const float*)d_in[4];
    const float* enc_embed = (const float*)d_in[5];
    const float* dec_embed = (const float*)d_in[6];
    const float* enc_Wih   = (const float*)d_in[7];
    const float* enc_Whh   = (const float*)d_in[8];
    const float* enc_b     = (const float*)d_in[9];
    const float* dec_Wih   = (const float*)d_in[10];
    const float* dec_Whh   = (const float*)d_in[11];
    const float* dec_b     = (const float*)d_in[12];
    const float* Tm        = (const float*)d_in[13];

    u16 *p_epad, *p_t, *p_xemb, *p_yemb, *p_gconv, *p_gdec, *p_wE, *p_wD, *p_Tb;
    u16 *p_hcat, *p_hdec, *p_Th;
    float *p_logits, *p_xz, *p_yz, *p_E;
    cudaGetSymbolAddress((void**)&p_epad, g_epad_bf);
    cudaGetSymbolAddress((void**)&p_t, g_t_bf);
    cudaGetSymbolAddress((void**)&p_xemb, g_xemb_bf);
    cudaGetSymbolAddress((void**)&p_yemb, g_yemb_bf);
    cudaGetSymbolAddress((void**)&p_gconv, g_gconv_bf);
    cudaGetSymbolAddress((void**)&p_gdec, g_gdec_bf);
    cudaGetSymbolAddress((void**)&p_wE, g_wihE_bf);
    cudaGetSymbolAddress((void**)&p_wD, g_wihD_bf);
    cudaGetSymbolAddress((void**)&p_Tb, g_T_bf);
    cudaGetSymbolAddress((void**)&p_hcat, g_hcat_bf);
    cudaGetSymbolAddress((void**)&p_hdec, g_hdec_bf);
    cudaGetSymbolAddress((void**)&p_Th, g_Th_bf);
    cudaGetSymbolAddress((void**)&p_logits, g_logits);
    cudaGetSymbolAddress((void**)&p_xz, g_xz);
    cudaGetSymbolAddress((void**)&p_yz, g_yz);
    cudaGetSymbolAddress((void**)&p_E, g_E);

    static cudaStream_t s1 = nullptr, s2 = nullptr, s3 = nullptr;
    static cudaEvent_t eStart = nullptr, eXZ = nullptr, eg = nullptr;
    static cudaEvent_t eFwd = nullptr, eBwd = nullptr, eth = nullptr, eYZ = nullptr, ePack = nullptr;
    static bool init_done = false;
    if (!init_done) {
        int prLo = 0, prHi = 0;
        cudaDeviceGetStreamPriorityRange(&prLo, &prHi);
        cudaStreamCreateWithPriority(&s1, cudaStreamNonBlocking, prLo);
        cudaStreamCreateWithPriority(&s2, cudaStreamNonBlocking, prHi);
        cudaStreamCreateWithPriority(&s3, cudaStreamNonBlocking, prHi);
        cudaEventCreateWithFlags(&eStart, cudaEventDisableTiming);
        cudaEventCreateWithFlags(&eXZ, cudaEventDisableTiming);
        cudaEventCreateWithFlags(&eg, cudaEventDisableTiming);
        cudaEventCreateWithFlags(&eFwd, cudaEventDisableTiming);
        cudaEventCreateWithFlags(&eBwd, cudaEventDisableTiming);
        cudaEventCreateWithFlags(&eth, cudaEventDisableTiming);
        cudaEventCreateWithFlags(&eYZ, cudaEventDisableTiming);
        cudaEventCreateWithFlags(&ePack, cudaEventDisableTiming);
        init_done = true;
    }

    // ---- capture-origin fork point: all side streams wait on eStart ----
    cudaEventRecord(eStart, 0);

    // ---- pack on s3 (off critical path; forked properly for graph capture) ----
    cudaStreamWaitEvent(s3, eStart, 0);
    k_pack<<<128, 256, 0, s3>>>(enc_Whh, dec_Whh);
    cudaEventRecord(ePack, s3);

    // ---- main stream: minimal critical-path prep (emb, xz) ----
    k_emb<<<(BB * NE * EE + 255) / 256, 256>>>(xs, ys, enc_embed, dec_embed);
    hgemm<2, true><<<dim3(8, 128, 1), 256>>>(p_xemb, 0, EE,
                                             p_wE, 0, EE,
                                             p_xz, 0, 4 * HH,
                                             BB * NE, 4 * HH, EE, enc_b);
    cudaEventRecord(eXZ, 0);

    // ---- yz on high-prio s2 (completes under fwd; dec gates on eYZ) ----
    cudaStreamWaitEvent(s2, eXZ, 0);
    hgemm<2, true><<<dim3(8, 128, 1), 256, 0, s2>>>(p_yemb, 0, EE,
                                                    p_wD, 0, EE,
                                                    p_yz, 0, 4 * HH,
                                                    BB * ND, 4 * HH, EE, dec_b);
    cudaEventRecord(eYZ, s2);

    // ---- backward encoder on s3 (after pack + xz), forward on main ----
    cudaStreamWaitEvent(s3, eXZ, 0);
    lstm_dir_mma<1><<<32, 512, 0, s3>>>();
    cudaEventRecord(eBwd, s3);

    cudaStreamWaitEvent(0, ePack, 0);
    lstm_dir_mma<0><<<32, 512>>>();
    cudaEventRecord(eFwd, 0);

    // ---- G-equivariant chain on low-priority s1: fills free SMs ----
    cudaStreamWaitEvent(s1, eXZ, 0);
    k_cvt<<<(FF * VOC + 255) / 256, 256, 0, s1>>>(gconv, gdecode, enc_Wih, dec_Wih, Tm);
    k_epad<<<(BB * 516 * FF + 255) / 256, 256, 0, s1>>>(xs, gembed);
    hgemm<1, false><<<dim3(2, 4, BB), 256, 0, s1>>>(p_epad, (size_t)516 * FF, FF,
                                                    p_gconv, 0, FF,
                                                    p_t, (size_t)NE * FF, FF,
                                                    NE, FF, 5 * FF, nullptr);
    hgemm<0, false><<<dim3(16, 128, 1), 256, 0, s1>>>(p_t, 0, FF,
                                                      p_gdec, 0, VOC,
                                                      p_logits, 0, VOC,
                                                      BB * NE, VOC, FF, nullptr);
    k_rowstats<<<BB * NE, 256, 0, s1>>>();
    k_scores<<<BB * ND, 512, 0, s1>>>(ys);
    cudaEventRecord(eg, s1);

    // Th = h_enc @ T^T — needs fwd + bwd; overlaps lstm_dec on s2
    cudaStreamWaitEvent(s2, eFwd, 0);
    cudaStreamWaitEvent(s2, eBwd, 0);
    hgemm<3, true><<<dim3(2, 4, BB), 256, 0, s2>>>(p_hcat, (size_t)NE * 2 * HH, 2 * HH,
                                                   p_Tb, 0, 2 * HH,
                                                   p_Th, (size_t)NE * HH, HH,
                                                   NE, HH, 2 * HH, nullptr);
    cudaEventRecord(eth, s2);

    // ---- decoder (needs fwd via stream order + yz) ----
    cudaStreamWaitEvent(0, eYZ, 0);
    lstm_dec_mma<<<32, 512>>>();

    // E[b][j][i] = h_dec[b][j] . Th[b][i]
    cudaStreamWaitEvent(0, eth, 0);
    hgemm<0, true><<<dim3(4, 4, BB), 256>>>(p_hdec, (size_t)ND * HH, HH,
                                            p_Th, (size_t)NE * HH, HH,
                                            p_E, (size_t)ND * NE, NE,
                                            ND, NE, HH, nullptr);

    cudaStreamWaitEvent(0, eg, 0);
    k_align<<<BB * ND, 256>>>();
    k_final<<<1, 1024>>>((float*)d_out);
}